// round 5
// baseline (speedup 1.0000x reference)
#include <cuda_runtime.h>
#include <cuda_fp16.h>
#include <cuda_bf16.h>

// HashEncoder: 4-level dense-grid trilinear interpolation, F=4.
// R5: (a) fp16 cell records (64B/cell, values pre-scaled by 2^12), layout per
// (cell, feature): 4 half2 groups g(dy*2+dx) = {c(dx,dy,z0), c(dx,dy,z1)}.
// (b) positions padded to float4 by a prep kernel, so encode fetches a
// point's xyz with ONE LDG.E.128 (1 L1 wavefront) instead of 3 scalar LDGs.
// Main kernel: 2 points per warp-slot (lane = q*16 + L*4 + f); x/y lerps in
// half2 SIMD, final z lerp + 2^-12 rescale in fp32.
//
// Level meta: res={32,43,56,74}, offsets={0,32768,112280,287896}, total=693120.

#define NPARAMS 693120
#define N_CAP   2097152
#define VAL_SCALE 4096.0f
#define INV_VAL_SCALE (1.0f / 4096.0f)

__device__ __half g_cells_h[NPARAMS * 32];   // 44.4 MB scratch (64B/cell)
__device__ float4 g_pos4[N_CAP];             // 32 MB padded positions

__constant__ int c_res[4] = {32, 43, 56, 74};
__constant__ int c_off[4] = {0, 32768, 112280, 287896};

// ---------------------------------------------------------------- prep: pad positions
__global__ void __launch_bounds__(256)
prep_pos(const float* __restrict__ pos, int n)
{
    int p = blockIdx.x * blockDim.x + threadIdx.x;
    if (p >= n || p >= N_CAP) return;
    float x = __ldg(&pos[3 * p + 0]);
    float y = __ldg(&pos[3 * p + 1]);
    float z = __ldg(&pos[3 * p + 2]);
    g_pos4[p] = make_float4(x, y, z, 0.0f);
}

// ---------------------------------------------------------------- preprocess table
// thread t = gbase*4 + f : writes 16B (4 half2 z-pair groups of feature f).
__global__ void __launch_bounds__(256)
build_cells(const float* __restrict__ tab)
{
    int t = blockIdx.x * blockDim.x + threadIdx.x;
    if (t >= NPARAMS * 4) return;

    int gbase = t >> 2;
    int f = t & 3;

    int L = (gbase >= 32768) + (gbase >= 112280) + (gbase >= 287896);
    int res  = c_res[L];
    int off  = c_off[L];
    int res2 = res * res;
    int local = gbase - off;

    int z   = local / res2;          // padding cells may exceed grid; clamp below
    int rem = local - z * res2;
    int y   = rem / res;
    int x   = rem - y * res;

    float v[4][2];
#pragma unroll
    for (int g = 0; g < 4; ++g) {
        int xi = min(x + (g & 1), res - 1);
        int yi = min(y + (g >> 1), res - 1);
#pragma unroll
        for (int dz = 0; dz < 2; ++dz) {
            int zi = min(z + dz, res - 1);
            int idx = off + xi + yi * res + zi * res2;
            v[g][dz] = __ldg(&tab[idx * 4 + f]) * VAL_SCALE;
        }
    }

    half2 h0 = __floats2half2_rn(v[0][0], v[0][1]);
    half2 h1 = __floats2half2_rn(v[1][0], v[1][1]);
    half2 h2 = __floats2half2_rn(v[2][0], v[2][1]);
    half2 h3 = __floats2half2_rn(v[3][0], v[3][1]);

    uint4 rec;
    rec.x = *(unsigned*)&h0;
    rec.y = *(unsigned*)&h1;
    rec.z = *(unsigned*)&h2;
    rec.w = *(unsigned*)&h3;
    ((uint4*)g_cells_h)[t] = rec;
}

// ---------------------------------------------------------------- main pass
template <bool GUARD>
__device__ __forceinline__ void
encode_body(float* __restrict__ out,
            const __half* __restrict__ cells_f, float s,
            int res, int res2, int off,
            int p0, int q, int lane, int n)
{
#pragma unroll
    for (int k = 0; k < 8; ++k) {
        int p = p0 + 2 * k + q;
        bool valid = true;
        if (GUARD) { valid = (p < n); if (!valid) p = n - 1; }

        float4 xyz = __ldg(&g_pos4[p]);   // one 16B load: whole position

        float px = fmaf(xyz.x, s, 0.5f);
        float py = fmaf(xyz.y, s, 0.5f);
        float pz = fmaf(xyz.z, s, 0.5f);
        float gx = floorf(px), gy = floorf(py), gz = floorf(pz);
        float fx = px - gx, fy = py - gy, fz = pz - gz;
        int ix = (int)gx, iy = (int)gy, iz = (int)gz;

        int gbase = off + ix + iy * res + iz * res2;

        // 16B: 4 half2 z-pair groups of this lane's feature.
        uint4 rec = __ldg((const uint4*)(cells_f + (size_t)gbase * 32));
        half2 g0 = *(half2*)&rec.x;   // (dx,dy)=(0,0)
        half2 g1 = *(half2*)&rec.y;   // (1,0)
        half2 g2 = *(half2*)&rec.z;   // (0,1)
        half2 g3 = *(half2*)&rec.w;   // (1,1)

        half2 fx2 = __float2half2_rn(fx);
        half2 fy2 = __float2half2_rn(fy);

        half2 a = __hfma2(fx2, __hsub2(g1, g0), g0);   // y=0, both z
        half2 b = __hfma2(fx2, __hsub2(g3, g2), g2);   // y=1, both z
        half2 c = __hfma2(fy2, __hsub2(b, a), a);      // {z0, z1}

        float clo = __low2float(c);
        float chi = __high2float(c);
        float r = fmaf(fz, chi - clo, clo) * INV_VAL_SCALE;

        if (!GUARD || valid)
            out[(size_t)p0 * 16 + 32 * k + lane] = r;
    }
}

__global__ void __launch_bounds__(256)
encode_kernel(float* __restrict__ out, float4 scales, int n)
{
    const int lane = threadIdx.x & 31;
    const int warp = (blockIdx.x * blockDim.x + threadIdx.x) >> 5;
    const int p0 = warp * 16;
    if (p0 >= n) return;

    const int q = lane >> 4;            // point parity within slot
    const int L = (lane >> 2) & 3;      // level
    const int f = lane & 3;             // feature

    const float s = (L < 2) ? (L == 0 ? scales.x : scales.y)
                            : (L == 2 ? scales.z : scales.w);
    const int res  = c_res[L];
    const int res2 = res * res;
    const int off  = c_off[L];
    const __half* cells_f = g_cells_h + f * 8;

    if (p0 + 16 <= n)
        encode_body<false>(out, cells_f, s, res, res2, off, p0, q, lane, n);
    else
        encode_body<true>(out, cells_f, s, res, res2, off, p0, q, lane, n);
}

// ---------------------------------------------------------------- launcher
extern "C" void kernel_launch(void* const* d_in, const int* in_sizes, int n_in,
                              void* d_out, int out_size)
{
    const float* positions = (const float*)d_in[0];
    const float* table = (const float*)d_in[1];
    float* out = (float*)d_out;

    int n = in_sizes[0] / 3;
    if (n > N_CAP) n = N_CAP;

    // Level scales: double math, rounded to fp32 like JAX's weak promotion.
    double b = 1.3195079565048218;
    double p = 1.0;
    float s[4];
    for (int l = 0; l < 4; ++l) {
        s[l] = (float)(32.0 * p - 1.0);
        p *= b;
    }
    float4 scales = make_float4(s[0], s[1], s[2], s[3]);

    int pb = (n + 255) / 256;
    prep_pos<<<pb, 256>>>(positions, n);

    int bb = (NPARAMS * 4 + 255) / 256;
    build_cells<<<bb, 256>>>(table);

    int warps = (n + 15) / 16;
    int blocks = (warps * 32 + 255) / 256;
    encode_kernel<<<blocks, 256>>>(out, scales, n);
}

// round 6
// speedup vs baseline: 1.1438x; 1.1438x over previous
#include <cuda_runtime.h>
#include <cuda_fp16.h>
#include <cuda_bf16.h>

// HashEncoder: 4-level dense-grid trilinear interpolation, F=4.
// R6 = R4 + smem position staging.
// fp16 cell records (64B/cell, values pre-scaled by 2^12). Per (cell,feature):
// 4 half2 groups g(dy*2+dx) = {c(dx,dy,z0), c(dx,dy,z1)}.
// Encode: block of 256 handles 128 points. Positions staged: coalesced float4
// gmem load -> smem raw -> repack to float4/point. Main loop reads xyz with
// ONE LDS.128 (1 wavefront) instead of 3 scalar LDGs. 2 points per warp-slot
// (lane = q*16 + L*4 + f); x/y lerps in half2 SIMD, z lerp + rescale in fp32.
//
// Level meta: res={32,43,56,74}, offsets={0,32768,112280,287896}, total=693120.

#define NPARAMS 693120
#define VAL_SCALE 4096.0f
#define INV_VAL_SCALE (1.0f / 4096.0f)

__device__ __half g_cells_h[NPARAMS * 32];   // 44.4 MB scratch (64B/cell)

__constant__ int c_res[4] = {32, 43, 56, 74};
__constant__ int c_off[4] = {0, 32768, 112280, 287896};

// ---------------------------------------------------------------- preprocess table
// thread t = gbase*4 + f : writes 16B (4 half2 z-pair groups of feature f).
__global__ void __launch_bounds__(256)
build_cells(const float* __restrict__ tab)
{
    int t = blockIdx.x * blockDim.x + threadIdx.x;
    if (t >= NPARAMS * 4) return;

    int gbase = t >> 2;
    int f = t & 3;

    int L = (gbase >= 32768) + (gbase >= 112280) + (gbase >= 287896);
    int res  = c_res[L];
    int off  = c_off[L];
    int res2 = res * res;
    int local = gbase - off;

    int z   = local / res2;          // padding cells may exceed grid; clamp below
    int rem = local - z * res2;
    int y   = rem / res;
    int x   = rem - y * res;

    float v[4][2];
#pragma unroll
    for (int g = 0; g < 4; ++g) {
        int xi = min(x + (g & 1), res - 1);
        int yi = min(y + (g >> 1), res - 1);
#pragma unroll
        for (int dz = 0; dz < 2; ++dz) {
            int zi = min(z + dz, res - 1);
            int idx = off + xi + yi * res + zi * res2;
            v[g][dz] = __ldg(&tab[idx * 4 + f]) * VAL_SCALE;
        }
    }

    half2 h0 = __floats2half2_rn(v[0][0], v[0][1]);
    half2 h1 = __floats2half2_rn(v[1][0], v[1][1]);
    half2 h2 = __floats2half2_rn(v[2][0], v[2][1]);
    half2 h3 = __floats2half2_rn(v[3][0], v[3][1]);

    uint4 rec;
    rec.x = *(unsigned*)&h0;
    rec.y = *(unsigned*)&h1;
    rec.z = *(unsigned*)&h2;
    rec.w = *(unsigned*)&h3;
    ((uint4*)g_cells_h)[t] = rec;
}

// ---------------------------------------------------------------- main pass
__global__ void __launch_bounds__(256)
encode_kernel(const float* __restrict__ pos, float* __restrict__ out,
              float4 scales, int n)
{
    __shared__ float  s_raw[384];     // 128 points * 3 floats
    __shared__ float4 s_pos4[128];    // padded positions

    const int t = threadIdx.x;
    const int bp0 = blockIdx.x * 128;          // first point of this block
    const long ftot = (long)n * 3;

    // Stage 1: coalesced gmem -> smem raw (96 float4 = 1536B).
    if (t < 96) {
        long fi = (long)bp0 * 3 + t * 4;
        if (fi + 4 <= ftot) {
            ((float4*)s_raw)[t] = ((const float4*)pos)[bp0 * 3 / 4 + t];
        } else {
#pragma unroll
            for (int j = 0; j < 4; ++j)
                s_raw[t * 4 + j] = (fi + j < ftot) ? pos[fi + j] : 0.0f;
        }
    }
    __syncthreads();

    // Stage 2: repack to float4 per point (stride-3 LDS: conflict-free).
    if (t < 128)
        s_pos4[t] = make_float4(s_raw[3 * t], s_raw[3 * t + 1], s_raw[3 * t + 2], 0.0f);
    __syncthreads();

    // Main loop: warp handles 16 points, 2 per slot.
    const int lane = t & 31;
    const int wl   = (t >> 5) * 16;            // warp's first local point
    const int q = lane >> 4;                   // point parity within slot
    const int L = (lane >> 2) & 3;             // level
    const int f = lane & 3;                    // feature

    const float s = (L < 2) ? (L == 0 ? scales.x : scales.y)
                            : (L == 2 ? scales.z : scales.w);
    const int res  = c_res[L];
    const int res2 = res * res;
    const int off  = c_off[L];
    const __half* cells_f = g_cells_h + f * 8;

    const bool full = (bp0 + 128 <= n);

#pragma unroll
    for (int k = 0; k < 8; ++k) {
        const int lp = wl + 2 * k + q;         // local point 0..127
        const int p  = bp0 + lp;
        if (!full && p >= n) continue;

        float4 xyz = s_pos4[lp];               // one LDS.128

        float px = fmaf(xyz.x, s, 0.5f);
        float py = fmaf(xyz.y, s, 0.5f);
        float pz = fmaf(xyz.z, s, 0.5f);
        float gx = floorf(px), gy = floorf(py), gz = floorf(pz);
        float fx = px - gx, fy = py - gy, fz = pz - gz;
        int ix = (int)gx, iy = (int)gy, iz = (int)gz;

        int gbase = off + ix + iy * res + iz * res2;

        // 16B: 4 half2 z-pair groups of this lane's feature.
        uint4 rec = __ldg((const uint4*)(cells_f + (size_t)gbase * 32));
        half2 g0 = *(half2*)&rec.x;   // (dx,dy)=(0,0)
        half2 g1 = *(half2*)&rec.y;   // (1,0)
        half2 g2 = *(half2*)&rec.z;   // (0,1)
        half2 g3 = *(half2*)&rec.w;   // (1,1)

        half2 fx2 = __float2half2_rn(fx);
        half2 fy2 = __float2half2_rn(fy);

        half2 a = __hfma2(fx2, __hsub2(g1, g0), g0);   // y=0, both z
        half2 b = __hfma2(fx2, __hsub2(g3, g2), g2);   // y=1, both z
        half2 c = __hfma2(fy2, __hsub2(b, a), a);      // {z0, z1}

        float clo = __low2float(c);
        float chi = __high2float(c);
        float r = fmaf(fz, chi - clo, clo) * INV_VAL_SCALE;

        // out[(bp0+lp)*16 + L*4+f], and lp = wl+2k+q
        out[(size_t)(bp0 + wl) * 16 + 32 * k + lane] = r;
    }
}

// ---------------------------------------------------------------- launcher
extern "C" void kernel_launch(void* const* d_in, const int* in_sizes, int n_in,
                              void* d_out, int out_size)
{
    const float* positions = (const float*)d_in[0];
    const float* table = (const float*)d_in[1];
    float* out = (float*)d_out;

    int n = in_sizes[0] / 3;

    // Level scales: double math, rounded to fp32 like JAX's weak promotion.
    double b = 1.3195079565048218;
    double p = 1.0;
    float s[4];
    for (int l = 0; l < 4; ++l) {
        s[l] = (float)(32.0 * p - 1.0);
        p *= b;
    }
    float4 scales = make_float4(s[0], s[1], s[2], s[3]);

    int bb = (NPARAMS * 4 + 255) / 256;
    build_cells<<<bb, 256>>>(table);

    int blocks = (n + 127) / 128;
    encode_kernel<<<blocks, 256>>>(positions, out, scales, n);
}

// round 7
// speedup vs baseline: 1.2092x; 1.0572x over previous
#include <cuda_runtime.h>
#include <cuda_fp16.h>
#include <cuda_bf16.h>

// HashEncoder: 4-level dense-grid trilinear interpolation, F=4.
// R7 = R4 encode with explicit 4-wide MLP batching + feature-pair build.
// fp16 cell records (64B/cell, values pre-scaled by 2^12). Per (cell,feature):
// 4 half2 groups g(dy*2+dx) = {c(dx,dy,z0), c(dx,dy,z1)}.
// Encode: 2 points per warp-slot (lane = q*16 + L*4 + f), 16 points/warp,
// slots processed in 2 batches of 4 so 4 pos-load->gather chains are in
// flight simultaneously. x/y lerps in half2 SIMD, z lerp + rescale in fp32.
//
// Level meta: res={32,43,56,74}, offsets={0,32768,112280,287896}, total=693120.

#define NPARAMS 693120
#define VAL_SCALE 4096.0f
#define INV_VAL_SCALE (1.0f / 4096.0f)

__device__ __half g_cells_h[NPARAMS * 32];   // 44.4 MB scratch (64B/cell)

__constant__ int c_res[4] = {32, 43, 56, 74};
__constant__ int c_off[4] = {0, 32768, 112280, 287896};

// ---------------------------------------------------------------- preprocess table
// thread t = gbase*2 + fp : builds records for features {2fp, 2fp+1}.
// Reads 8 float2 (both features of each corner), writes 2 uint4 (32B).
__global__ void __launch_bounds__(256)
build_cells(const float* __restrict__ tab)
{
    int t = blockIdx.x * blockDim.x + threadIdx.x;
    if (t >= NPARAMS * 2) return;

    int gbase = t >> 1;
    int fp = t & 1;                  // feature pair: features 2fp, 2fp+1

    int L = (gbase >= 32768) + (gbase >= 112280) + (gbase >= 287896);
    int res  = c_res[L];
    int off  = c_off[L];
    int res2 = res * res;
    int local = gbase - off;

    int z   = local / res2;          // padding cells may exceed grid; clamp below
    int rem = local - z * res2;
    int y   = rem / res;
    int x   = rem - y * res;

    // v[g][dz] = float2(feat 2fp, feat 2fp+1), g = dy*2 + dx
    float2 v[4][2];
#pragma unroll
    for (int g = 0; g < 4; ++g) {
        int xi = min(x + (g & 1), res - 1);
        int yi = min(y + (g >> 1), res - 1);
#pragma unroll
        for (int dz = 0; dz < 2; ++dz) {
            int zi = min(z + dz, res - 1);
            int idx = off + xi + yi * res + zi * res2;
            float2 w = __ldg((const float2*)&tab[idx * 4 + 2 * fp]);
            v[g][dz] = make_float2(w.x * VAL_SCALE, w.y * VAL_SCALE);
        }
    }

    // Feature 2fp record: group g = half2(z0, z1) of feature.x
    uint4 r0, r1;
    {
        half2 h0 = __floats2half2_rn(v[0][0].x, v[0][1].x);
        half2 h1 = __floats2half2_rn(v[1][0].x, v[1][1].x);
        half2 h2 = __floats2half2_rn(v[2][0].x, v[2][1].x);
        half2 h3 = __floats2half2_rn(v[3][0].x, v[3][1].x);
        r0.x = *(unsigned*)&h0; r0.y = *(unsigned*)&h1;
        r0.z = *(unsigned*)&h2; r0.w = *(unsigned*)&h3;
    }
    {
        half2 h0 = __floats2half2_rn(v[0][0].y, v[0][1].y);
        half2 h1 = __floats2half2_rn(v[1][0].y, v[1][1].y);
        half2 h2 = __floats2half2_rn(v[2][0].y, v[2][1].y);
        half2 h3 = __floats2half2_rn(v[3][0].y, v[3][1].y);
        r1.x = *(unsigned*)&h0; r1.y = *(unsigned*)&h1;
        r1.z = *(unsigned*)&h2; r1.w = *(unsigned*)&h3;
    }

    uint4* dst = (uint4*)g_cells_h;
    dst[gbase * 4 + 2 * fp]     = r0;
    dst[gbase * 4 + 2 * fp + 1] = r1;
}

// ---------------------------------------------------------------- main pass
template <bool GUARD>
__device__ __forceinline__ void
encode_body(const float* __restrict__ pos, float* __restrict__ out,
            const __half* __restrict__ cells_f, float s,
            int res, int res2, int off,
            int p0, int q, int lane, int n)
{
#pragma unroll
    for (int kb = 0; kb < 2; ++kb) {
        // ---- phase 1: 4 position loads in flight
        float X[4], Y[4], Z[4];
#pragma unroll
        for (int j = 0; j < 4; ++j) {
            int p = p0 + 2 * (kb * 4 + j) + q;
            if (GUARD && p >= n) p = n - 1;
            X[j] = __ldg(&pos[3 * p + 0]);
            Y[j] = __ldg(&pos[3 * p + 1]);
            Z[j] = __ldg(&pos[3 * p + 2]);
        }

        // ---- phase 2: transforms + 4 gather loads in flight
        float FX[4], FY[4], FZ[4];
        uint4 R[4];
#pragma unroll
        for (int j = 0; j < 4; ++j) {
            float px = fmaf(X[j], s, 0.5f);
            float py = fmaf(Y[j], s, 0.5f);
            float pz = fmaf(Z[j], s, 0.5f);
            float gx = floorf(px), gy = floorf(py), gz = floorf(pz);
            FX[j] = px - gx; FY[j] = py - gy; FZ[j] = pz - gz;
            int ix = (int)gx, iy = (int)gy, iz = (int)gz;
            int gbase = off + ix + iy * res + iz * res2;
            R[j] = __ldg((const uint4*)(cells_f + (size_t)gbase * 32));
        }

        // ---- phase 3: math + stores
#pragma unroll
        for (int j = 0; j < 4; ++j) {
            half2 g0 = *(half2*)&R[j].x;   // (dx,dy)=(0,0), {z0,z1}
            half2 g1 = *(half2*)&R[j].y;   // (1,0)
            half2 g2 = *(half2*)&R[j].z;   // (0,1)
            half2 g3 = *(half2*)&R[j].w;   // (1,1)

            half2 fx2 = __float2half2_rn(FX[j]);
            half2 fy2 = __float2half2_rn(FY[j]);

            half2 a = __hfma2(fx2, __hsub2(g1, g0), g0);
            half2 b = __hfma2(fx2, __hsub2(g3, g2), g2);
            half2 c = __hfma2(fy2, __hsub2(b, a), a);   // {z0, z1}

            float clo = __low2float(c);
            float chi = __high2float(c);
            float r = fmaf(FZ[j], chi - clo, clo) * INV_VAL_SCALE;

            int k = kb * 4 + j;
            if (!GUARD || (p0 + 2 * k + q) < n)
                out[(size_t)p0 * 16 + 32 * k + lane] = r;
        }
    }
}

__global__ void __launch_bounds__(256, 4)
encode_kernel(const float* __restrict__ pos, float* __restrict__ out,
              float4 scales, int n)
{
    const int lane = threadIdx.x & 31;
    const int warp = (blockIdx.x * blockDim.x + threadIdx.x) >> 5;
    const int p0 = warp * 16;
    if (p0 >= n) return;

    const int q = lane >> 4;            // point parity within slot
    const int L = (lane >> 2) & 3;      // level
    const int f = lane & 3;             // feature

    const float s = (L < 2) ? (L == 0 ? scales.x : scales.y)
                            : (L == 2 ? scales.z : scales.w);
    const int res  = c_res[L];
    const int res2 = res * res;
    const int off  = c_off[L];
    const __half* cells_f = g_cells_h + f * 8;

    if (p0 + 16 <= n)
        encode_body<false>(pos, out, cells_f, s, res, res2, off, p0, q, lane, n);
    else
        encode_body<true>(pos, out, cells_f, s, res, res2, off, p0, q, lane, n);
}

// ---------------------------------------------------------------- launcher
extern "C" void kernel_launch(void* const* d_in, const int* in_sizes, int n_in,
                              void* d_out, int out_size)
{
    const float* positions = (const float*)d_in[0];
    const float* table = (const float*)d_in[1];
    float* out = (float*)d_out;

    int n = in_sizes[0] / 3;

    // Level scales: double math, rounded to fp32 like JAX's weak promotion.
    double b = 1.3195079565048218;
    double p = 1.0;
    float s[4];
    for (int l = 0; l < 4; ++l) {
        s[l] = (float)(32.0 * p - 1.0);
        p *= b;
    }
    float4 scales = make_float4(s[0], s[1], s[2], s[3]);

    int bb = (NPARAMS * 2 + 255) / 256;
    build_cells<<<bb, 256>>>(table);

    int warps = (n + 15) / 16;
    int blocks = (warps * 32 + 255) / 256;
    encode_kernel<<<blocks, 256>>>(positions, out, scales, n);
}